// round 1
// baseline (speedup 1.0000x reference)
#include <cuda_runtime.h>
#include <math_constants.h>

#define NVEC   16384
#define KCODES 8192
#define CDIM   256
#define ZELEMS (16*256*32*32)   /* 4194304 */

__device__ float  g_zz[NVEC];
__device__ float  g_ee[KCODES];
__device__ int    g_idx[NVEC];
__device__ double g_loss;

// ---------------------------------------------------------------------------
// zz[n] = sum_c z[n][c]^2  (sequential, mul-then-add, matching reference fp32)
// ee[k] = sum_c e[k][c]^2
// z layout: [b][c][hw] with b=n>>10, hw=n&1023  -> z_flat[n][c] = z[b*262144 + c*1024 + hw]
// ---------------------------------------------------------------------------
__global__ void prologue_kernel(const float* __restrict__ z,
                                const float* __restrict__ emb) {
    int i = blockIdx.x * blockDim.x + threadIdx.x;
    if (i == 0) g_loss = 0.0;
    if (i < NVEC) {
        int b = i >> 10, hw = i & 1023;
        const float* p = z + (size_t)b * 262144 + hw;
        float acc = 0.f;
        #pragma unroll 8
        for (int c = 0; c < CDIM; c++) {
            float v = p[(size_t)c * 1024];
            acc = __fadd_rn(acc, __fmul_rn(v, v));
        }
        g_zz[i] = acc;
    } else if (i < NVEC + KCODES) {
        int k = i - NVEC;
        const float* p = emb + (size_t)k * CDIM;
        float acc = 0.f;
        #pragma unroll 8
        for (int c = 0; c < CDIM; c++) {
            float v = p[c];
            acc = __fadd_rn(acc, __fmul_rn(v, v));
        }
        g_ee[k] = acc;
    }
}

// ---------------------------------------------------------------------------
// Fused distance-GEMM + argmin. Block: 64 n-rows x all K. 256 threads (16x16),
// 4x4 frags. zs: [256 c][64 n] resident panel. es: [32 c][64 k] chunk with
// XOR swizzle (kk ^ 4*(c/4 & 7)) -> conflict-free transpose STS and LDS.128.
// dot accumulated c=0..255 with sequential fmaf (matches reference ordering),
// d = fl(fl(zz+ee) - fl(2*dot)) with forced rn ops, strict-< argmin,
// first-(smallest)-index tie break.
// ---------------------------------------------------------------------------
__global__ __launch_bounds__(256, 2)
void argmin_kernel(const float* __restrict__ z, const float* __restrict__ emb) {
    extern __shared__ float smem[];
    float* zs = smem;             // 16384 floats  (64 KB)
    float* es = smem + 16384;     // 2048  floats  (8 KB)
    float* sd = es + 2048;        // 1024  floats
    int*   si = (int*)(sd + 1024);// 1024  ints

    const int t  = threadIdx.x;
    const int tx = t & 15, ty = t >> 4;
    const int n0 = blockIdx.x * 64;
    const int b  = n0 >> 10, hw0 = n0 & 1023;

    // load z panel: 4096 float4s, coalesced (z is c-major per batch)
    const float4* zg = (const float4*)(z + (size_t)b * 262144 + hw0);
    for (int v = t; v < 4096; v += 256) {
        int c = v >> 4, r4 = v & 15;
        float4 w = zg[c * 256 + r4];
        *(float4*)&zs[c * 64 + r4 * 4] = w;
    }
    __syncthreads();

    float zzr[4];
    #pragma unroll
    for (int i = 0; i < 4; i++) zzr[i] = g_zz[n0 + ty * 4 + i];

    float bestd[4]; int bestk[4];
    #pragma unroll
    for (int i = 0; i < 4; i++) { bestd[i] = CUDART_INF_F; bestk[i] = 0; }

    for (int kt = 0; kt < KCODES / 64; kt++) {
        const int k0 = kt * 64;
        float acc[4][4];
        #pragma unroll
        for (int i = 0; i < 4; i++)
            #pragma unroll
            for (int j = 0; j < 4; j++) acc[i][j] = 0.f;

        for (int ch = 0; ch < 8; ch++) {
            const int c0 = ch * 32;
            __syncthreads();
            // load+transpose emb chunk [64 k][32 c] -> es[c][kk^swz]
            #pragma unroll
            for (int vv = 0; vv < 2; vv++) {
                int v  = t + vv * 256;
                int kk = v >> 3, c4 = v & 7;
                float4 w = *(const float4*)(emb + (size_t)(k0 + kk) * 256 + c0 + c4 * 4);
                int sw = c4 * 4;                 // = 4*(c_local/4), c_local = 4*c4+u
                int col = kk ^ sw;
                es[(c4 * 4 + 0) * 64 + col] = w.x;
                es[(c4 * 4 + 1) * 64 + col] = w.y;
                es[(c4 * 4 + 2) * 64 + col] = w.z;
                es[(c4 * 4 + 3) * 64 + col] = w.w;
            }
            __syncthreads();
            #pragma unroll
            for (int c = 0; c < 32; c++) {
                float4 zf = *(const float4*)&zs[(c0 + c) * 64 + ty * 4];
                int sw = ((c >> 2) & 7) * 4;
                float4 ef = *(const float4*)&es[c * 64 + ((tx * 4) ^ sw)];
                float zv[4] = { zf.x, zf.y, zf.z, zf.w };
                float ev[4] = { ef.x, ef.y, ef.z, ef.w };
                #pragma unroll
                for (int i = 0; i < 4; i++)
                    #pragma unroll
                    for (int j = 0; j < 4; j++)
                        acc[i][j] = fmaf(zv[i], ev[j], acc[i][j]);
            }
        }
        // epilogue: rounded distance + running argmin (k ascending per thread)
        #pragma unroll
        for (int j = 0; j < 4; j++) {
            int k = k0 + tx * 4 + j;
            float eek = g_ee[k];
            #pragma unroll
            for (int i = 0; i < 4; i++) {
                float d = __fsub_rn(__fadd_rn(zzr[i], eek),
                                    __fmul_rn(2.0f, acc[i][j]));
                if (d < bestd[i]) { bestd[i] = d; bestk[i] = k; }
            }
        }
    }

    __syncthreads();
    #pragma unroll
    for (int i = 0; i < 4; i++) {
        sd[(ty * 4 + i) * 16 + tx] = bestd[i];
        si[(ty * 4 + i) * 16 + tx] = bestk[i];
    }
    __syncthreads();
    if (t < 64) {
        float bd = CUDART_INF_F; int bk = 0x7fffffff;
        for (int x = 0; x < 16; x++) {
            float d = sd[t * 16 + x];
            int   k = si[t * 16 + x];
            if (d < bd || (d == bd && k < bk)) { bd = d; bk = k; }
        }
        g_idx[n0 + t] = bk;
    }
}

// ---------------------------------------------------------------------------
// out[o] = fl(z + fl(zq - z))  (straight-through; intermediate rounding matters)
// loss accumulation: sum of fl(zq - z)^2 via block reduce + double atomic.
// o = b*262144 + c*1024 + hw  (identity with both z and out layouts)
// ---------------------------------------------------------------------------
__global__ void gather_kernel(const float* __restrict__ z,
                              const float* __restrict__ emb,
                              float* __restrict__ out) {
    int o = blockIdx.x * 256 + threadIdx.x;
    int rem = o & 262143;
    int b  = o >> 18;
    int c  = rem >> 10;
    int hw = rem & 1023;
    int n  = (b << 10) + hw;
    float zv = z[o];
    float q  = emb[(size_t)g_idx[n] * CDIM + c];
    float diff = __fsub_rn(q, zv);
    out[o] = __fadd_rn(zv, diff);
    float d2 = __fmul_rn(diff, diff);

    __shared__ float red[256];
    red[threadIdx.x] = d2;
    __syncthreads();
    for (int s = 128; s > 0; s >>= 1) {
        if (threadIdx.x < s) red[threadIdx.x] += red[threadIdx.x + s];
        __syncthreads();
    }
    if (threadIdx.x == 0) atomicAdd(&g_loss, (double)red[0]);
}

__global__ void tail_kernel(float* __restrict__ out, int out_size) {
    int i = blockIdx.x * 256 + threadIdx.x;
    if (i < NVEC && out_size >= ZELEMS + NVEC)
        out[ZELEMS + i] = (float)g_idx[i];
    if (i == 0 && out_size >= ZELEMS + NVEC + 1) {
        float m = (float)(g_loss / (double)ZELEMS);
        out[ZELEMS + NVEC] = __fadd_rn(m, __fmul_rn(0.25f, m)); // m + BETA*m
    }
}

// ---------------------------------------------------------------------------
extern "C" void kernel_launch(void* const* d_in, const int* in_sizes, int n_in,
                              void* d_out, int out_size) {
    const float* z   = (const float*)d_in[0];
    const float* emb = (const float*)d_in[1];
    float* out = (float*)d_out;

    cudaFuncSetAttribute(argmin_kernel,
                         cudaFuncAttributeMaxDynamicSharedMemorySize, 81920);

    prologue_kernel<<<(NVEC + KCODES + 255) / 256, 256>>>(z, emb);
    argmin_kernel<<<NVEC / 64, 256, 81920>>>(z, emb);
    gather_kernel<<<ZELEMS / 256, 256>>>(z, emb, out);
    tail_kernel<<<(NVEC + 255) / 256, 256>>>(out, out_size);
}

// round 2
// speedup vs baseline: 1.1570x; 1.1570x over previous
#include <cuda_runtime.h>
#include <math_constants.h>

#define NVEC   16384
#define KCODES 8192
#define CDIM   256
#define ZELEMS (16*256*32*32)   /* 4194304 */

__device__ float  g_zz[NVEC];
__device__ float  g_ee[KCODES];
__device__ int    g_idx[NVEC];
__device__ double g_loss;

typedef unsigned long long ull;

__device__ __forceinline__ ull pack_dup(float x) {
    ull r; unsigned u = __float_as_uint(x);
    asm("mov.b64 %0, {%1, %1};" : "=l"(r) : "r"(u));
    return r;
}
__device__ __forceinline__ void fma2(ull& d, ull a, ull b) {
    asm("fma.rn.f32x2 %0, %1, %2, %0;" : "+l"(d) : "l"(a), "l"(b));
}
__device__ __forceinline__ void unpack2(float& lo, float& hi, ull v) {
    unsigned a, b;
    asm("mov.b64 {%0, %1}, %2;" : "=r"(a), "=r"(b) : "l"(v));
    lo = __uint_as_float(a); hi = __uint_as_float(b);
}

// ---------------------------------------------------------------------------
// zz[n] = sum_c z[n][c]^2 ; ee[k] = sum_c e[k][c]^2  (sequential fp32 fma order)
// z layout: [b][c][hw], b=n>>10, hw=n&1023
// ---------------------------------------------------------------------------
__global__ void prologue_kernel(const float* __restrict__ z,
                                const float* __restrict__ emb) {
    int i = blockIdx.x * blockDim.x + threadIdx.x;
    if (i == 0) g_loss = 0.0;
    if (i < NVEC) {
        int b = i >> 10, hw = i & 1023;
        const float* p = z + (size_t)b * 262144 + hw;
        float acc = 0.f;
        #pragma unroll 8
        for (int c = 0; c < CDIM; c++) {
            float v = p[(size_t)c * 1024];
            acc = __fadd_rn(acc, __fmul_rn(v, v));
        }
        g_zz[i] = acc;
    } else if (i < NVEC + KCODES) {
        int k = i - NVEC;
        const float* p = emb + (size_t)k * CDIM;
        float acc = 0.f;
        #pragma unroll 8
        for (int c = 0; c < CDIM; c++) {
            float v = p[c];
            acc = __fadd_rn(acc, __fmul_rn(v, v));
        }
        g_ee[k] = acc;
    }
}

// ---------------------------------------------------------------------------
// Fused distance GEMM + argmin, FFMA2 (f32x2) mainloop.
// Block tile: 64 n rows (resident z panel, 64KB) x 128 k per tile, all K looped.
// 256 threads: tx = t&31 (k, 4 per thread), ty = t>>5 (n, 8 per thread).
// acc[p][j] : p = n-pair (0..3 -> rows ty*8+2p, +2p+1), j = k (tx*4+j).
// es double-buffered [2][32c][128k] with XOR swizzle; z pairs free via LDS.128.
// Arithmetic per scalar lane identical to the verified bit-exact R1 path.
// ---------------------------------------------------------------------------
__global__ __launch_bounds__(256, 2)
void argmin_kernel(const float* __restrict__ z, const float* __restrict__ emb) {
    extern __shared__ float smem[];
    float* zs = smem;               // 16384 floats (64 KB)
    float* es = smem + 16384;       // 2 x 4096 floats (32 KB), double buffer
    float* sd = es;                 // overlap after mainloop: 2048 floats
    int*   si = (int*)(es + 2048);  // 2048 ints

    const int t  = threadIdx.x;
    const int tx = t & 31, ty = t >> 5;
    const int n0 = blockIdx.x * 64;
    const int b  = n0 >> 10, hw0 = n0 & 1023;

    // resident z panel: [256 c][64 n], coalesced (z is c-major per batch)
    const float4* zg = (const float4*)(z + (size_t)b * 262144 + hw0);
    for (int v = t; v < 4096; v += 256) {
        int c = v >> 4, r4 = v & 15;
        *(float4*)&zs[c * 64 + r4 * 4] = zg[c * 256 + r4];
    }

    float bestd[8]; int bestk[8];
    #pragma unroll
    for (int i = 0; i < 8; i++) { bestd[i] = CUDART_INF_F; bestk[i] = 0; }

    // loader thread-constants: v = t + vv*256 -> kk = v>>3, c4 = v&7
    const int kk_b = t >> 3;      // + 32*vv
    const int c4_l = t & 7;
    const int sw_l = ((c4_l & 1) << 4) | ((c4_l >> 1) << 2);

    float4 pre[4];

    #pragma unroll 1
    for (int kt = 0; kt < KCODES / 128; kt++) {
        const int k0 = kt * 128;

        ull acc[4][4];
        #pragma unroll
        for (int p = 0; p < 4; p++)
            #pragma unroll
            for (int j = 0; j < 4; j++) acc[p][j] = 0ull;

        // prefetch + store ch0 into buf0
        #pragma unroll
        for (int vv = 0; vv < 4; vv++)
            pre[vv] = *(const float4*)(emb + (size_t)(k0 + kk_b + 32 * vv) * 256 + c4_l * 4);
        #pragma unroll
        for (int vv = 0; vv < 4; vv++) {
            int kk = kk_b + 32 * vv;
            float* eb = es + (c4_l * 4) * 128 + (kk ^ sw_l);
            eb[0 * 128] = pre[vv].x; eb[1 * 128] = pre[vv].y;
            eb[2 * 128] = pre[vv].z; eb[3 * 128] = pre[vv].w;
        }
        __syncthreads();   // also covers z panel on kt==0

        #pragma unroll 1
        for (int ch = 0; ch < 8; ch++) {
            const int c0 = ch * 32;
            if (ch < 7) {
                int c0n = c0 + 32;
                #pragma unroll
                for (int vv = 0; vv < 4; vv++)
                    pre[vv] = *(const float4*)(emb + (size_t)(k0 + kk_b + 32 * vv) * 256 + c0n + c4_l * 4);
            }
            const float* esb = es + (ch & 1) * 4096;

            #pragma unroll 8
            for (int c = 0; c < 32; c++) {
                int cc = c0 + c;
                int sw = (((c >> 2) & 1) << 4) | ((c >> 3) << 2);
                ull zp01 = *(const ull*)&zs[cc * 64 + ty * 8];
                ull zp23 = *(const ull*)&zs[cc * 64 + ty * 8 + 2];
                ull zp45 = *(const ull*)&zs[cc * 64 + ty * 8 + 4];
                ull zp67 = *(const ull*)&zs[cc * 64 + ty * 8 + 6];
                float4 ef = *(const float4*)&esb[c * 128 + ((tx * 4) ^ sw)];
                ull e0 = pack_dup(ef.x), e1 = pack_dup(ef.y);
                ull e2 = pack_dup(ef.z), e3 = pack_dup(ef.w);
                fma2(acc[0][0], zp01, e0); fma2(acc[0][1], zp01, e1);
                fma2(acc[0][2], zp01, e2); fma2(acc[0][3], zp01, e3);
                fma2(acc[1][0], zp23, e0); fma2(acc[1][1], zp23, e1);
                fma2(acc[1][2], zp23, e2); fma2(acc[1][3], zp23, e3);
                fma2(acc[2][0], zp45, e0); fma2(acc[2][1], zp45, e1);
                fma2(acc[2][2], zp45, e2); fma2(acc[2][3], zp45, e3);
                fma2(acc[3][0], zp67, e0); fma2(acc[3][1], zp67, e1);
                fma2(acc[3][2], zp67, e2); fma2(acc[3][3], zp67, e3);
            }

            if (ch < 7) {
                float* ebuf = es + ((ch + 1) & 1) * 4096;
                #pragma unroll
                for (int vv = 0; vv < 4; vv++) {
                    int kk = kk_b + 32 * vv;
                    float* eb = ebuf + (c4_l * 4) * 128 + (kk ^ sw_l);
                    eb[0 * 128] = pre[vv].x; eb[1 * 128] = pre[vv].y;
                    eb[2 * 128] = pre[vv].z; eb[3 * 128] = pre[vv].w;
                }
                __syncthreads();
            }
        }

        // epilogue: rounded distance + running argmin (k ascending in time)
        #pragma unroll
        for (int j = 0; j < 4; j++) {
            int k = k0 + tx * 4 + j;
            float eek = g_ee[k];
            #pragma unroll
            for (int p = 0; p < 4; p++) {
                float dlo, dhi;
                unpack2(dlo, dhi, acc[p][j]);
                float zzl = g_zz[n0 + ty * 8 + 2 * p];
                float zzh = g_zz[n0 + ty * 8 + 2 * p + 1];
                float d0 = __fsub_rn(__fadd_rn(zzl, eek), __fmul_rn(2.0f, dlo));
                float d1 = __fsub_rn(__fadd_rn(zzh, eek), __fmul_rn(2.0f, dhi));
                if (d0 < bestd[2 * p])     { bestd[2 * p] = d0;     bestk[2 * p] = k; }
                if (d1 < bestd[2 * p + 1]) { bestd[2 * p + 1] = d1; bestk[2 * p + 1] = k; }
            }
        }
    }

    __syncthreads();   // es dead; reuse as reduction scratch
    #pragma unroll
    for (int i = 0; i < 8; i++) {
        sd[(ty * 8 + i) * 32 + tx] = bestd[i];
        si[(ty * 8 + i) * 32 + tx] = bestk[i];
    }
    __syncthreads();
    if (t < 64) {
        float bd = CUDART_INF_F; int bk = 0x7fffffff;
        for (int x = 0; x < 32; x++) {
            float d = sd[t * 32 + x];
            int   k = si[t * 32 + x];
            if (d < bd || (d == bd && k < bk)) { bd = d; bk = k; }
        }
        g_idx[n0 + t] = bk;
    }
}

// ---------------------------------------------------------------------------
// out[o] = fl(z + fl(zq - z)) ; loss = sum fl(zq-z)^2 (double atomics)
// ---------------------------------------------------------------------------
__global__ void gather_kernel(const float* __restrict__ z,
                              const float* __restrict__ emb,
                              float* __restrict__ out) {
    int o = blockIdx.x * 256 + threadIdx.x;
    int rem = o & 262143;
    int b  = o >> 18;
    int c  = rem >> 10;
    int hw = rem & 1023;
    int n  = (b << 10) + hw;
    float zv = z[o];
    float q  = emb[(size_t)g_idx[n] * CDIM + c];
    float diff = __fsub_rn(q, zv);
    out[o] = __fadd_rn(zv, diff);
    float d2 = __fmul_rn(diff, diff);

    __shared__ float red[256];
    red[threadIdx.x] = d2;
    __syncthreads();
    for (int s = 128; s > 0; s >>= 1) {
        if (threadIdx.x < s) red[threadIdx.x] += red[threadIdx.x + s];
        __syncthreads();
    }
    if (threadIdx.x == 0) atomicAdd(&g_loss, (double)red[0]);
}

__global__ void tail_kernel(float* __restrict__ out, int out_size) {
    int i = blockIdx.x * 256 + threadIdx.x;
    if (i < NVEC && out_size >= ZELEMS + NVEC)
        out[ZELEMS + i] = (float)g_idx[i];
    if (i == 0 && out_size >= ZELEMS + NVEC + 1) {
        float m = (float)(g_loss / (double)ZELEMS);
        out[ZELEMS + NVEC] = __fadd_rn(m, __fmul_rn(0.25f, m)); // m + BETA*m
    }
}

// ---------------------------------------------------------------------------
extern "C" void kernel_launch(void* const* d_in, const int* in_sizes, int n_in,
                              void* d_out, int out_size) {
    const float* z   = (const float*)d_in[0];
    const float* emb = (const float*)d_in[1];
    float* out = (float*)d_out;

    cudaFuncSetAttribute(argmin_kernel,
                         cudaFuncAttributeMaxDynamicSharedMemorySize, 98304);

    prologue_kernel<<<(NVEC + KCODES + 255) / 256, 256>>>(z, emb);
    argmin_kernel<<<NVEC / 64, 256, 98304>>>(z, emb);
    gather_kernel<<<ZELEMS / 256, 256>>>(z, emb, out);
    tail_kernel<<<(NVEC + 255) / 256, 256>>>(out, out_size);
}